// round 1
// baseline (speedup 1.0000x reference)
#include <cuda_runtime.h>
#include <math.h>

#define Bsz 128
#define Tsz 256
#define Isz 512
#define Hsz 1024
#define Mpre (Bsz*Tsz)

#define BM 128
#define BN 64
#define BK 16

// ---------------- scratch (static device allocations; no cudaMalloc) --------
__device__ float g_P[5][Mpre][Hsz];          // gate preactivations from x / x_d (+bias)
__device__ float g_HS[(size_t)Mpre*Hsz];     // all hidden states, (b*T+t, h)
__device__ float g_h[2][Bsz*Hsz];            // ping-pong hidden
__device__ float g_c[Bsz*Hsz];               // cell state

// ---------------- helpers ---------------------------------------------------
__device__ __forceinline__ float to_tf32(float x){
    float r; asm("cvt.rna.tf32.f32 %0, %1;" : "=f"(r) : "f"(x)); return r;
}
__device__ __forceinline__ void mma8(float c[4], const float a[4], const float b[2]){
    asm volatile("mma.sync.aligned.m16n8k8.row.col.f32.tf32.tf32.f32 "
        "{%0,%1,%2,%3},{%4,%5,%6,%7},{%8,%9},{%0,%1,%2,%3};"
        : "+f"(c[0]),"+f"(c[1]),"+f"(c[2]),"+f"(c[3])
        : "r"(__float_as_uint(a[0])),"r"(__float_as_uint(a[1])),
          "r"(__float_as_uint(a[2])),"r"(__float_as_uint(a[3])),
          "r"(__float_as_uint(b[0])),"r"(__float_as_uint(b[1])));
}
__device__ __forceinline__ float sig_(float x){ return 1.f/(1.f+expf(-x)); }

// ---------------- shared GEMM panel: C(128x64) += A(m0..,K) * W(n0..,K)^T ---
__device__ __forceinline__ void gemm_panel(
    const float* __restrict__ A, int lda,
    const float* __restrict__ W, int ldw,
    int K, int m0, int n0, int tid,
    float (&cacc)[2][4][4],
    float (&As)[BM][BK+1], float (&Bs)[BN][BK+1])
{
    const int lane = tid & 31, wid = tid >> 5;
    const int wm = wid & 3, wn = wid >> 2;        // 4 x 2 warp grid
    const int gid = lane >> 2, tig = lane & 3;

    for (int k0 = 0; k0 < K; k0 += BK) {
        // A tile: 128x16 floats (512 float4)
        for (int i = tid; i < BM*(BK/4); i += 256) {
            int r = i >> 2, c4 = (i & 3) * 4;
            float4 v = *reinterpret_cast<const float4*>(A + (size_t)(m0+r)*lda + k0 + c4);
            As[r][c4+0]=to_tf32(v.x); As[r][c4+1]=to_tf32(v.y);
            As[r][c4+2]=to_tf32(v.z); As[r][c4+3]=to_tf32(v.w);
        }
        // W tile: 64x16 floats (256 float4)
        for (int i = tid; i < BN*(BK/4); i += 256) {
            int r = i >> 2, c4 = (i & 3) * 4;
            float4 v = *reinterpret_cast<const float4*>(W + (size_t)(n0+r)*ldw + k0 + c4);
            Bs[r][c4+0]=to_tf32(v.x); Bs[r][c4+1]=to_tf32(v.y);
            Bs[r][c4+2]=to_tf32(v.z); Bs[r][c4+3]=to_tf32(v.w);
        }
        __syncthreads();
        #pragma unroll
        for (int kk = 0; kk < 2; kk++) {
            float a[2][4], bf2[4][2];
            #pragma unroll
            for (int mt = 0; mt < 2; mt++) {
                int rb = wm*32 + mt*16;
                a[mt][0] = As[rb+gid  ][kk*8+tig  ];
                a[mt][1] = As[rb+gid+8][kk*8+tig  ];
                a[mt][2] = As[rb+gid  ][kk*8+tig+4];
                a[mt][3] = As[rb+gid+8][kk*8+tig+4];
            }
            #pragma unroll
            for (int nt = 0; nt < 4; nt++) {
                int nb = wn*32 + nt*8;
                bf2[nt][0] = Bs[nb+gid][kk*8+tig  ];
                bf2[nt][1] = Bs[nb+gid][kk*8+tig+4];
            }
            #pragma unroll
            for (int mt = 0; mt < 2; mt++)
                #pragma unroll
                for (int nt = 0; nt < 4; nt++)
                    mma8(cacc[mt][nt], a[mt], bf2[nt]);
        }
        __syncthreads();
    }
}

// ---------------- phase A: P_g = X_g @ W_g^T + b_g --------------------------
__global__ __launch_bounds__(256)
void gemm_pre(const float* __restrict__ x, const float* __restrict__ xd,
              const float* __restrict__ W0, const float* __restrict__ W1,
              const float* __restrict__ W2, const float* __restrict__ W3,
              const float* __restrict__ W4,
              const float* __restrict__ b0, const float* __restrict__ b1,
              const float* __restrict__ b2, const float* __restrict__ b3,
              const float* __restrict__ b4)
{
    __shared__ float As[BM][BK+1];
    __shared__ float Bs[BN][BK+1];
    const int gate = blockIdx.z;
    const float* A    = (gate == 4) ? xd : x;
    const float* W    = gate==0?W0 : gate==1?W1 : gate==2?W2 : gate==3?W3 : W4;
    const float* bias = gate==0?b0 : gate==1?b1 : gate==2?b2 : gate==3?b3 : b4;
    const int m0 = blockIdx.y * BM;
    const int n0 = blockIdx.x * BN;
    const int tid = threadIdx.x;

    float cacc[2][4][4];
    #pragma unroll
    for (int i=0;i<2;i++) for (int j=0;j<4;j++) for (int k=0;k<4;k++) cacc[i][j][k]=0.f;

    gemm_panel(A, Isz, W, Isz, Isz, m0, n0, tid, cacc, As, Bs);

    const int lane = tid & 31, wid = tid >> 5;
    const int wm = wid & 3, wn = wid >> 2;
    const int gid = lane >> 2, tig = lane & 3;
    #pragma unroll
    for (int mt=0; mt<2; mt++)
        #pragma unroll
        for (int nt=0; nt<4; nt++) {
            int row = m0 + wm*32 + mt*16 + gid;
            int col = n0 + wn*32 + nt*8 + 2*tig;
            float bv0 = bias[col], bv1 = bias[col+1];
            g_P[gate][row  ][col  ] = cacc[mt][nt][0] + bv0;
            g_P[gate][row  ][col+1] = cacc[mt][nt][1] + bv1;
            g_P[gate][row+8][col  ] = cacc[mt][nt][2] + bv0;
            g_P[gate][row+8][col+1] = cacc[mt][nt][3] + bv1;
        }
}

// ---------------- phase B: one timestep, all gates + state update -----------
#define SBK 32
__global__ __launch_bounds__(256)
void lstm_step(int t, int cur,
               const float* __restrict__ Whi, const float* __restrict__ Whf,
               const float* __restrict__ Whg, const float* __restrict__ Who,
               const float* __restrict__ Whd)
{
    __shared__ float Hs[128][SBK+1];
    __shared__ float Ws[5][8][SBK+1];
    const int h0  = blockIdx.x * 8;
    const int tid = threadIdx.x, lane = tid & 31, wid = tid >> 5;
    const int gid = lane >> 2, tig = lane & 3;
    const float* __restrict__ hprev = g_h[cur];

    float cacc[5][4];
    #pragma unroll
    for (int g=0; g<5; g++) { cacc[g][0]=0.f; cacc[g][1]=0.f; cacc[g][2]=0.f; cacc[g][3]=0.f; }

    for (int k0 = 0; k0 < Hsz; k0 += SBK) {
        // h_prev tile: 128 x 32 (1024 float4)
        for (int i = tid; i < 128*(SBK/4); i += 256) {
            int r = i >> 3, c4 = (i & 7) * 4;
            float4 v = *reinterpret_cast<const float4*>(hprev + (size_t)r*Hsz + k0 + c4);
            Hs[r][c4+0]=to_tf32(v.x); Hs[r][c4+1]=to_tf32(v.y);
            Hs[r][c4+2]=to_tf32(v.z); Hs[r][c4+3]=to_tf32(v.w);
        }
        // weight tiles: 5 gates x 8 rows x 32 (320 float4)
        for (int i = tid; i < 5*8*(SBK/4); i += 256) {
            int rr = i >> 3, c4 = (i & 7) * 4;
            int g = rr >> 3, n = rr & 7;
            const float* Wg = g==0?Whi : g==1?Whf : g==2?Whg : g==3?Who : Whd;
            float4 v = *reinterpret_cast<const float4*>(Wg + (size_t)(h0+n)*Hsz + k0 + c4);
            Ws[g][n][c4+0]=to_tf32(v.x); Ws[g][n][c4+1]=to_tf32(v.y);
            Ws[g][n][c4+2]=to_tf32(v.z); Ws[g][n][c4+3]=to_tf32(v.w);
        }
        __syncthreads();
        #pragma unroll
        for (int kk = 0; kk < SBK/8; kk++) {
            float a[4];
            int rb = wid * 16;
            a[0] = Hs[rb+gid  ][kk*8+tig  ];
            a[1] = Hs[rb+gid+8][kk*8+tig  ];
            a[2] = Hs[rb+gid  ][kk*8+tig+4];
            a[3] = Hs[rb+gid+8][kk*8+tig+4];
            #pragma unroll
            for (int g = 0; g < 5; g++) {
                float bfr[2];
                bfr[0] = Ws[g][gid][kk*8+tig  ];
                bfr[1] = Ws[g][gid][kk*8+tig+4];
                mma8(cacc[g], a, bfr);
            }
        }
        __syncthreads();
    }

    // gate nonlinearities + state update
    const int nxt = cur ^ 1;
    #pragma unroll
    for (int j = 0; j < 4; j++) {
        int b = wid*16 + gid + ((j >> 1) ? 8 : 0);
        int h = h0 + 2*tig + (j & 1);
        int m = b*Tsz + t;
        float pi = cacc[0][j] + g_P[0][m][h];
        float pf = cacc[1][j] + g_P[1][m][h];
        float pg = cacc[2][j] + g_P[2][m][h];
        float po = cacc[3][j] + g_P[3][m][h];
        float pd = cacc[4][j] + g_P[4][m][h];
        float iv = sig_(pi), fv = sig_(pf), gv = tanhf(pg);
        float ov = sig_(po), dv = sig_(pd);
        float cp = g_c[b*Hsz + h];
        float cn = fv*cp + iv*gv + dv;
        float hn = ov * tanhf(cn);
        g_c[b*Hsz + h]      = cn;
        g_h[nxt][b*Hsz + h] = hn;
        g_HS[(size_t)m*Hsz + h] = hn;
    }
}

// ---------------- phase C: y = tanh(X@Wro^T + HS@Who^T + Wrb) ---------------
__global__ __launch_bounds__(256)
void gemm_out(const float* __restrict__ x, const float* __restrict__ Wro,
              const float* __restrict__ Who, const float* __restrict__ Wrb,
              float* __restrict__ y)
{
    __shared__ float As[BM][BK+1];
    __shared__ float Bs[BN][BK+1];
    const int m0 = blockIdx.y * BM;
    const int n0 = blockIdx.x * BN;
    const int tid = threadIdx.x;

    float cacc[2][4][4];
    #pragma unroll
    for (int i=0;i<2;i++) for (int j=0;j<4;j++) for (int k=0;k<4;k++) cacc[i][j][k]=0.f;

    gemm_panel(x,      Isz, Wro, Isz, Isz, m0, n0, tid, cacc, As, Bs);
    gemm_panel(&g_HS[0], Hsz, Who, Hsz, Hsz, m0, n0, tid, cacc, As, Bs);

    const int lane = tid & 31, wid = tid >> 5;
    const int wm = wid & 3, wn = wid >> 2;
    const int gid = lane >> 2, tig = lane & 3;
    #pragma unroll
    for (int mt=0; mt<2; mt++)
        #pragma unroll
        for (int nt=0; nt<4; nt++) {
            int row = m0 + wm*32 + mt*16 + gid;
            int col = n0 + wn*32 + nt*8 + 2*tig;
            float bv0 = Wrb[col], bv1 = Wrb[col+1];
            y[(size_t)row*Hsz + col  ]     = tanhf(cacc[mt][nt][0] + bv0);
            y[(size_t)row*Hsz + col+1]     = tanhf(cacc[mt][nt][1] + bv1);
            y[(size_t)(row+8)*Hsz + col  ] = tanhf(cacc[mt][nt][2] + bv0);
            y[(size_t)(row+8)*Hsz + col+1] = tanhf(cacc[mt][nt][3] + bv1);
        }
}

// ---------------- small state init / tail copy ------------------------------
__global__ void init_state(const float* __restrict__ hidden, const float* __restrict__ cell){
    int i = blockIdx.x * 256 + threadIdx.x;
    g_h[0][i] = hidden[i];
    g_c[i]    = cell[i];
}
__global__ void write_tail(float* __restrict__ out){
    int i = blockIdx.x * 256 + threadIdx.x;
    out[(size_t)Bsz*Tsz*Hsz + i]              = g_h[0][i];
    out[(size_t)Bsz*Tsz*Hsz + Bsz*Hsz + i]    = g_c[i];
}

// ---------------- launcher ---------------------------------------------------
extern "C" void kernel_launch(void* const* d_in, const int* in_sizes, int n_in,
                              void* d_out, int out_size)
{
    const float *x, *xd, *hidden, *cell;
    const float *Wii,*Wif,*Wig,*Wio,*Wid,*Wro,*Whi,*Whf,*Whg,*Who,*Whd;
    const float *bi,*bf,*bg,*bo,*bd,*Wrb;

    x      = (const float*)d_in[0];
    xd     = (const float*)d_in[1];
    hidden = (const float*)d_in[2];
    cell   = (const float*)d_in[3];

    if (in_sizes[5] == Hsz*Isz) {
        // setup_inputs dict order: Wii,Wif,Wig,Wio,Wid,Wro, Whi..Whd, bi..bd,Wrb
        Wii=(const float*)d_in[4];  Wif=(const float*)d_in[5];  Wig=(const float*)d_in[6];
        Wio=(const float*)d_in[7];  Wid=(const float*)d_in[8];  Wro=(const float*)d_in[9];
        Whi=(const float*)d_in[10]; Whf=(const float*)d_in[11]; Whg=(const float*)d_in[12];
        Who=(const float*)d_in[13]; Whd=(const float*)d_in[14];
        bi=(const float*)d_in[15];  bf=(const float*)d_in[16];  bg=(const float*)d_in[17];
        bo=(const float*)d_in[18];  bd=(const float*)d_in[19];  Wrb=(const float*)d_in[20];
    } else {
        // reference signature order
        Wii=(const float*)d_in[4];  Whi=(const float*)d_in[5];  bi =(const float*)d_in[6];
        Wif=(const float*)d_in[7];  Whf=(const float*)d_in[8];  bf =(const float*)d_in[9];
        Wig=(const float*)d_in[10]; Whg=(const float*)d_in[11]; bg =(const float*)d_in[12];
        Wio=(const float*)d_in[13]; Who=(const float*)d_in[14]; bo =(const float*)d_in[15];
        Wid=(const float*)d_in[16]; Whd=(const float*)d_in[17]; bd =(const float*)d_in[18];
        Wro=(const float*)d_in[19]; Wrb=(const float*)d_in[20];
    }

    float* out = (float*)d_out;

    init_state<<<(Bsz*Hsz)/256, 256>>>(hidden, cell);

    dim3 gpre(Hsz/BN, Mpre/BM, 5);
    gemm_pre<<<gpre, 256>>>(x, xd, Wii, Wif, Wig, Wio, Wid, bi, bf, bg, bo, bd);

    for (int t = 0; t < Tsz; t++)
        lstm_step<<<Hsz/8, 256>>>(t, t & 1, Whi, Whf, Whg, Who, Whd);

    gemm_out<<<dim3(Hsz/BN, Mpre/BM), 256>>>(x, Wro, Who, Wrb, out);

    write_tail<<<(Bsz*Hsz)/256, 256>>>(out);
}

// round 2
// speedup vs baseline: 3.1434x; 3.1434x over previous
#include <cuda_runtime.h>
#include <math.h>

#define Bsz 128
#define Tsz 256
#define Isz 512
#define Hsz 1024
#define Mpre (Bsz*Tsz)

#define BM 128
#define BN 64
#define BK 16

// ---------------- scratch (static device allocations; no cudaMalloc) --------
__device__ float g_P[5][Tsz][Bsz][Hsz];      // gate preactivations, [g][t][b][h]
__device__ float g_HS[(size_t)Mpre*Hsz];     // all hidden states, (b*T+t, h)
__device__ float g_h[2][Bsz*Hsz];            // ping-pong hidden
__device__ float g_c[Bsz*Hsz];               // cell state

// ---------------- helpers ---------------------------------------------------
__device__ __forceinline__ float to_tf32(float x){
    float r; asm("cvt.rna.tf32.f32 %0, %1;" : "=f"(r) : "f"(x)); return r;
}
__device__ __forceinline__ void mma8(float c[4], const float a[4], const float b[2]){
    asm volatile("mma.sync.aligned.m16n8k8.row.col.f32.tf32.tf32.f32 "
        "{%0,%1,%2,%3},{%4,%5,%6,%7},{%8,%9},{%0,%1,%2,%3};"
        : "+f"(c[0]),"+f"(c[1]),"+f"(c[2]),"+f"(c[3])
        : "r"(__float_as_uint(a[0])),"r"(__float_as_uint(a[1])),
          "r"(__float_as_uint(a[2])),"r"(__float_as_uint(a[3])),
          "r"(__float_as_uint(b[0])),"r"(__float_as_uint(b[1])));
}
__device__ __forceinline__ float sig_(float x){ return 1.f/(1.f+expf(-x)); }

// ---------------- shared GEMM panel: C(128x64) += A(m0..,K) * W(n0..,K)^T ---
__device__ __forceinline__ void gemm_panel(
    const float* __restrict__ A, int lda,
    const float* __restrict__ W, int ldw,
    int K, int m0, int n0, int tid,
    float (&cacc)[2][4][4],
    float (&As)[BM][BK+1], float (&Bs)[BN][BK+1])
{
    const int lane = tid & 31, wid = tid >> 5;
    const int wm = wid & 3, wn = wid >> 2;        // 4 x 2 warp grid
    const int gid = lane >> 2, tig = lane & 3;

    for (int k0 = 0; k0 < K; k0 += BK) {
        for (int i = tid; i < BM*(BK/4); i += 256) {
            int r = i >> 2, c4 = (i & 3) * 4;
            float4 v = *reinterpret_cast<const float4*>(A + (size_t)(m0+r)*lda + k0 + c4);
            As[r][c4+0]=to_tf32(v.x); As[r][c4+1]=to_tf32(v.y);
            As[r][c4+2]=to_tf32(v.z); As[r][c4+3]=to_tf32(v.w);
        }
        for (int i = tid; i < BN*(BK/4); i += 256) {
            int r = i >> 2, c4 = (i & 3) * 4;
            float4 v = *reinterpret_cast<const float4*>(W + (size_t)(n0+r)*ldw + k0 + c4);
            Bs[r][c4+0]=to_tf32(v.x); Bs[r][c4+1]=to_tf32(v.y);
            Bs[r][c4+2]=to_tf32(v.z); Bs[r][c4+3]=to_tf32(v.w);
        }
        __syncthreads();
        #pragma unroll
        for (int kk = 0; kk < 2; kk++) {
            float a[2][4], bf2[4][2];
            #pragma unroll
            for (int mt = 0; mt < 2; mt++) {
                int rb = wm*32 + mt*16;
                a[mt][0] = As[rb+gid  ][kk*8+tig  ];
                a[mt][1] = As[rb+gid+8][kk*8+tig  ];
                a[mt][2] = As[rb+gid  ][kk*8+tig+4];
                a[mt][3] = As[rb+gid+8][kk*8+tig+4];
            }
            #pragma unroll
            for (int nt = 0; nt < 4; nt++) {
                int nb = wn*32 + nt*8;
                bf2[nt][0] = Bs[nb+gid][kk*8+tig  ];
                bf2[nt][1] = Bs[nb+gid][kk*8+tig+4];
            }
            #pragma unroll
            for (int mt = 0; mt < 2; mt++)
                #pragma unroll
                for (int nt = 0; nt < 4; nt++)
                    mma8(cacc[mt][nt], a[mt], bf2[nt]);
        }
        __syncthreads();
    }
}

// ---------------- phase A: P_g = X_g @ W_g^T + b_g --------------------------
__global__ __launch_bounds__(256)
void gemm_pre(const float* __restrict__ x, const float* __restrict__ xd,
              const float* __restrict__ W0, const float* __restrict__ W1,
              const float* __restrict__ W2, const float* __restrict__ W3,
              const float* __restrict__ W4,
              const float* __restrict__ b0, const float* __restrict__ b1,
              const float* __restrict__ b2, const float* __restrict__ b3,
              const float* __restrict__ b4)
{
    __shared__ float As[BM][BK+1];
    __shared__ float Bs[BN][BK+1];
    const int gate = blockIdx.z;
    const float* A    = (gate == 4) ? xd : x;
    const float* W    = gate==0?W0 : gate==1?W1 : gate==2?W2 : gate==3?W3 : W4;
    const float* bias = gate==0?b0 : gate==1?b1 : gate==2?b2 : gate==3?b3 : b4;
    const int m0 = blockIdx.y * BM;
    const int n0 = blockIdx.x * BN;
    const int tid = threadIdx.x;

    float cacc[2][4][4];
    #pragma unroll
    for (int i=0;i<2;i++) for (int j=0;j<4;j++) for (int k=0;k<4;k++) cacc[i][j][k]=0.f;

    gemm_panel(A, Isz, W, Isz, Isz, m0, n0, tid, cacc, As, Bs);

    const int lane = tid & 31, wid = tid >> 5;
    const int wm = wid & 3, wn = wid >> 2;
    const int gid = lane >> 2, tig = lane & 3;
    #pragma unroll
    for (int mt=0; mt<2; mt++)
        #pragma unroll
        for (int nt=0; nt<4; nt++) {
            int row = m0 + wm*32 + mt*16 + gid;
            int b = row >> 8;         // row / Tsz
            int tt = row & 255;       // row % Tsz  (row+8 stays in same b)
            int col = n0 + wn*32 + nt*8 + 2*tig;
            float bv0 = bias[col], bv1 = bias[col+1];
            g_P[gate][tt  ][b][col  ] = cacc[mt][nt][0] + bv0;
            g_P[gate][tt  ][b][col+1] = cacc[mt][nt][1] + bv1;
            g_P[gate][tt+8][b][col  ] = cacc[mt][nt][2] + bv0;
            g_P[gate][tt+8][b][col+1] = cacc[mt][nt][3] + bv1;
        }
}

// ---------------- phase B: one timestep, all gates + state update -----------
// 128 CTAs, each owns 8 h-columns x 5 gates (40 output cols) over all 128 batches.
// Warp layout: wm = wid&3 -> 32 batch rows; kh = wid>>2 -> k-half split.
// SMEM: ping-pong tiles, row stride 36 (conflict-free frag reads).
#define SBK 32
#define HSTR 36
#define SM_HS(buf) ((buf)*4608)            /* 128*36 floats per buf */
#define SM_WS(buf) (9216 + (buf)*1440)     /* 40*36 floats per buf  */

__global__ __launch_bounds__(256)
void lstm_step(int t, int cur,
               const float* __restrict__ Whi, const float* __restrict__ Whf,
               const float* __restrict__ Whg, const float* __restrict__ Who,
               const float* __restrict__ Whd)
{
    __shared__ float sm[12096];   // 48,384 bytes
    const int h0  = blockIdx.x * 8;
    const int tid = threadIdx.x, lane = tid & 31, wid = tid >> 5;
    const int gid = lane >> 2, tig = lane & 3;
    const int wm  = wid & 3;
    const int kh  = wid >> 2;
    const float* __restrict__ hprev = g_h[cur];

    // per-thread load coordinates
    const int ar  = tid >> 3;            // A row base (j advances rows by 32)
    const int ac4 = (tid & 7) * 4;       // column within 32-wide k tile
    // W row j=0: rows 0..31 -> gates 0..3
    const int wr0   = tid >> 3;
    const int wg0   = wr0 >> 3;
    const float* Wp0 = wg0==0 ? Whi : wg0==1 ? Whf : wg0==2 ? Whg : Who;
    const float* Wrow0 = Wp0 + (size_t)(h0 + (wr0 & 7)) * Hsz + ac4;
    // W row j=1: rows 32..39 -> gate 4 (only tid < 64)
    const bool hasw1 = (tid < 64);
    const float* Wrow1 = Whd + (size_t)(h0 + (wr0 & 7)) * Hsz + ac4;

    float cacc[2][5][4];
    #pragma unroll
    for (int mt=0; mt<2; mt++)
        #pragma unroll
        for (int g=0; g<5; g++)
            { cacc[mt][g][0]=0.f; cacc[mt][g][1]=0.f; cacc[mt][g][2]=0.f; cacc[mt][g][3]=0.f; }

    float4 ra[4], rw0, rw1;
    rw1 = make_float4(0.f,0.f,0.f,0.f);

    // ---- prologue: load tile 0, store to buf 0 ----
    #pragma unroll
    for (int j=0; j<4; j++)
        ra[j] = *reinterpret_cast<const float4*>(hprev + (size_t)(ar + j*32)*Hsz + ac4);
    rw0 = *reinterpret_cast<const float4*>(Wrow0);
    if (hasw1) rw1 = *reinterpret_cast<const float4*>(Wrow1);

    #pragma unroll
    for (int j=0; j<4; j++) {
        float* p = &sm[SM_HS(0) + (ar + j*32)*HSTR + ac4];
        p[0]=to_tf32(ra[j].x); p[1]=to_tf32(ra[j].y); p[2]=to_tf32(ra[j].z); p[3]=to_tf32(ra[j].w);
    }
    {
        float* p = &sm[SM_WS(0) + wr0*HSTR + ac4];
        p[0]=to_tf32(rw0.x); p[1]=to_tf32(rw0.y); p[2]=to_tf32(rw0.z); p[3]=to_tf32(rw0.w);
        if (hasw1) {
            float* q = &sm[SM_WS(0) + (32 + wr0)*HSTR + ac4];
            q[0]=to_tf32(rw1.x); q[1]=to_tf32(rw1.y); q[2]=to_tf32(rw1.z); q[3]=to_tf32(rw1.w);
        }
    }
    __syncthreads();

    // ---- main loop: 32 k-tiles of 32, ping-pong, 1 sync/iter ----
    for (int k0 = 0; k0 < Hsz/SBK; k0++) {
        const int buf = k0 & 1;
        if (k0 < Hsz/SBK - 1) {
            const int kb = (k0+1)*SBK;
            #pragma unroll
            for (int j=0; j<4; j++)
                ra[j] = *reinterpret_cast<const float4*>(hprev + (size_t)(ar + j*32)*Hsz + kb + ac4);
            rw0 = *reinterpret_cast<const float4*>(Wrow0 + kb);
            if (hasw1) rw1 = *reinterpret_cast<const float4*>(Wrow1 + kb);
        }

        const float* HS_ = &sm[SM_HS(buf)];
        const float* WS_ = &sm[SM_WS(buf)];
        #pragma unroll
        for (int kk = 0; kk < 2; kk++) {
            const int kb = kh*16 + kk*8;
            float a[2][4];
            #pragma unroll
            for (int mt=0; mt<2; mt++) {
                const float* hp = HS_ + (wm*32 + mt*16 + gid)*HSTR + kb;
                a[mt][0] = hp[tig];
                a[mt][1] = hp[8*HSTR + tig];
                a[mt][2] = hp[tig+4];
                a[mt][3] = hp[8*HSTR + tig+4];
            }
            #pragma unroll
            for (int g=0; g<5; g++) {
                const float* bp = WS_ + (g*8 + gid)*HSTR + kb;
                float br[2] = { bp[tig], bp[tig+4] };
                mma8(cacc[0][g], a[0], br);
                mma8(cacc[1][g], a[1], br);
            }
        }

        if (k0 < Hsz/SBK - 1) {
            const int nb = buf ^ 1;
            #pragma unroll
            for (int j=0; j<4; j++) {
                float* p = &sm[SM_HS(nb) + (ar + j*32)*HSTR + ac4];
                p[0]=to_tf32(ra[j].x); p[1]=to_tf32(ra[j].y); p[2]=to_tf32(ra[j].z); p[3]=to_tf32(ra[j].w);
            }
            float* p = &sm[SM_WS(nb) + wr0*HSTR + ac4];
            p[0]=to_tf32(rw0.x); p[1]=to_tf32(rw0.y); p[2]=to_tf32(rw0.z); p[3]=to_tf32(rw0.w);
            if (hasw1) {
                float* q = &sm[SM_WS(nb) + (32 + wr0)*HSTR + ac4];
                q[0]=to_tf32(rw1.x); q[1]=to_tf32(rw1.y); q[2]=to_tf32(rw1.z); q[3]=to_tf32(rw1.w);
            }
        }
        __syncthreads();
    }

    // ---- cross-k-half reduction via SMEM ----
    if (kh == 1) {
        float* sr = &sm[wm*1312 + lane*41];      // 32*41 = 1312
        #pragma unroll
        for (int mt=0; mt<2; mt++)
            #pragma unroll
            for (int g=0; g<5; g++)
                #pragma unroll
                for (int r=0; r<4; r++)
                    sr[mt*20 + g*4 + r] = cacc[mt][g][r];
    }
    __syncthreads();

    if (kh == 0) {
        const float* sr = &sm[wm*1312 + lane*41];
        #pragma unroll
        for (int mt=0; mt<2; mt++)
            #pragma unroll
            for (int g=0; g<5; g++)
                #pragma unroll
                for (int r=0; r<4; r++)
                    cacc[mt][g][r] += sr[mt*20 + g*4 + r];

        const int nxt = cur ^ 1;
        #pragma unroll
        for (int mt=0; mt<2; mt++)
            #pragma unroll
            for (int r=0; r<4; r++) {
                int b = wm*32 + mt*16 + gid + ((r >> 1) ? 8 : 0);
                int h = h0 + 2*tig + (r & 1);
                float pi = cacc[mt][0][r] + g_P[0][t][b][h];
                float pf = cacc[mt][1][r] + g_P[1][t][b][h];
                float pg = cacc[mt][2][r] + g_P[2][t][b][h];
                float po = cacc[mt][3][r] + g_P[3][t][b][h];
                float pd = cacc[mt][4][r] + g_P[4][t][b][h];
                float iv = sig_(pi), fv = sig_(pf), gv = tanhf(pg);
                float ov = sig_(po), dv = sig_(pd);
                float cp = g_c[b*Hsz + h];
                float cn = fv*cp + iv*gv + dv;
                float hn = ov * tanhf(cn);
                g_c[b*Hsz + h]      = cn;
                g_h[nxt][b*Hsz + h] = hn;
                g_HS[((size_t)b*Tsz + t)*Hsz + h] = hn;
            }
    }
}

// ---------------- phase C: y = tanh(X@Wro^T + HS@Who^T + Wrb) ---------------
__global__ __launch_bounds__(256)
void gemm_out(const float* __restrict__ x, const float* __restrict__ Wro,
              const float* __restrict__ Who, const float* __restrict__ Wrb,
              float* __restrict__ y)
{
    __shared__ float As[BM][BK+1];
    __shared__ float Bs[BN][BK+1];
    const int m0 = blockIdx.y * BM;
    const int n0 = blockIdx.x * BN;
    const int tid = threadIdx.x;

    float cacc[2][4][4];
    #pragma unroll
    for (int i=0;i<2;i++) for (int j=0;j<4;j++) for (int k=0;k<4;k++) cacc[i][j][k]=0.f;

    gemm_panel(x,        Isz, Wro, Isz, Isz, m0, n0, tid, cacc, As, Bs);
    gemm_panel(&g_HS[0], Hsz, Who, Hsz, Hsz, m0, n0, tid, cacc, As, Bs);

    const int lane = tid & 31, wid = tid >> 5;
    const int wm = wid & 3, wn = wid >> 2;
    const int gid = lane >> 2, tig = lane & 3;
    #pragma unroll
    for (int mt=0; mt<2; mt++)
        #pragma unroll
        for (int nt=0; nt<4; nt++) {
            int row = m0 + wm*32 + mt*16 + gid;
            int col = n0 + wn*32 + nt*8 + 2*tig;
            float bv0 = Wrb[col], bv1 = Wrb[col+1];
            y[(size_t)row*Hsz + col  ]     = tanhf(cacc[mt][nt][0] + bv0);
            y[(size_t)row*Hsz + col+1]     = tanhf(cacc[mt][nt][1] + bv1);
            y[(size_t)(row+8)*Hsz + col  ] = tanhf(cacc[mt][nt][2] + bv0);
            y[(size_t)(row+8)*Hsz + col+1] = tanhf(cacc[mt][nt][3] + bv1);
        }
}

// ---------------- small state init / tail copy ------------------------------
__global__ void init_state(const float* __restrict__ hidden, const float* __restrict__ cell){
    int i = blockIdx.x * 256 + threadIdx.x;
    g_h[0][i] = hidden[i];
    g_c[i]    = cell[i];
}
__global__ void write_tail(float* __restrict__ out){
    int i = blockIdx.x * 256 + threadIdx.x;
    out[(size_t)Bsz*Tsz*Hsz + i]              = g_h[0][i];
    out[(size_t)Bsz*Tsz*Hsz + Bsz*Hsz + i]    = g_c[i];
}

// ---------------- launcher ---------------------------------------------------
extern "C" void kernel_launch(void* const* d_in, const int* in_sizes, int n_in,
                              void* d_out, int out_size)
{
    const float *x, *xd, *hidden, *cell;
    const float *Wii,*Wif,*Wig,*Wio,*Wid,*Wro,*Whi,*Whf,*Whg,*Who,*Whd;
    const float *bi,*bf,*bg,*bo,*bd,*Wrb;

    x      = (const float*)d_in[0];
    xd     = (const float*)d_in[1];
    hidden = (const float*)d_in[2];
    cell   = (const float*)d_in[3];

    if (in_sizes[5] == Hsz*Isz) {
        // setup_inputs dict order
        Wii=(const float*)d_in[4];  Wif=(const float*)d_in[5];  Wig=(const float*)d_in[6];
        Wio=(const float*)d_in[7];  Wid=(const float*)d_in[8];  Wro=(const float*)d_in[9];
        Whi=(const float*)d_in[10]; Whf=(const float*)d_in[11]; Whg=(const float*)d_in[12];
        Who=(const float*)d_in[13]; Whd=(const float*)d_in[14];
        bi=(const float*)d_in[15];  bf=(const float*)d_in[16];  bg=(const float*)d_in[17];
        bo=(const float*)d_in[18];  bd=(const float*)d_in[19];  Wrb=(const float*)d_in[20];
    } else {
        // reference signature order
        Wii=(const float*)d_in[4];  Whi=(const float*)d_in[5];  bi =(const float*)d_in[6];
        Wif=(const float*)d_in[7];  Whf=(const float*)d_in[8];  bf =(const float*)d_in[9];
        Wig=(const float*)d_in[10]; Whg=(const float*)d_in[11]; bg =(const float*)d_in[12];
        Wio=(const float*)d_in[13]; Who=(const float*)d_in[14]; bo =(const float*)d_in[15];
        Wid=(const float*)d_in[16]; Whd=(const float*)d_in[17]; bd =(const float*)d_in[18];
        Wro=(const float*)d_in[19]; Wrb=(const float*)d_in[20];
    }

    float* out = (float*)d_out;

    init_state<<<(Bsz*Hsz)/256, 256>>>(hidden, cell);

    dim3 gpre(Hsz/BN, Mpre/BM, 5);
    gemm_pre<<<gpre, 256>>>(x, xd, Wii, Wif, Wig, Wio, Wid, bi, bf, bg, bo, bd);

    for (int t = 0; t < Tsz; t++)
        lstm_step<<<Hsz/8, 256>>>(t, t & 1, Whi, Whf, Whg, Who, Whd);

    gemm_out<<<dim3(Hsz/BN, Mpre/BM), 256>>>(x, Wro, Who, Wrb, out);

    write_tail<<<(Bsz*Hsz)/256, 256>>>(out);
}

// round 3
// speedup vs baseline: 3.2461x; 1.0327x over previous
#include <cuda_runtime.h>
#include <math.h>

#define Bsz 128
#define Tsz 256
#define Isz 512
#define Hsz 1024
#define Mpre (Bsz*Tsz)

#define BM 128
#define BN 64
#define BK 16

// ---------------- scratch (static device allocations; no cudaMalloc) --------
__device__ float g_P[5][Tsz][Bsz][Hsz];      // gate preactivations, [g][t][b][h]
__device__ float g_HS[(size_t)Mpre*Hsz];     // all hidden states, (b*T+t, h)
__device__ float g_h[2][Bsz*Hsz];            // ping-pong hidden
__device__ float g_c[Bsz*Hsz];               // cell state
__device__ int   g_flag[Bsz*8];              // producer flags, 32B padded

// ---------------- helpers ---------------------------------------------------
__device__ __forceinline__ float to_tf32(float x){
    float r; asm("cvt.rna.tf32.f32 %0, %1;" : "=f"(r) : "f"(x)); return r;
}
__device__ __forceinline__ void mma8(float c[4], const float a[4], const float b[2]){
    asm volatile("mma.sync.aligned.m16n8k8.row.col.f32.tf32.tf32.f32 "
        "{%0,%1,%2,%3},{%4,%5,%6,%7},{%8,%9},{%0,%1,%2,%3};"
        : "+f"(c[0]),"+f"(c[1]),"+f"(c[2]),"+f"(c[3])
        : "r"(__float_as_uint(a[0])),"r"(__float_as_uint(a[1])),
          "r"(__float_as_uint(a[2])),"r"(__float_as_uint(a[3])),
          "r"(__float_as_uint(b[0])),"r"(__float_as_uint(b[1])));
}
__device__ __forceinline__ float sig_(float x){ return 1.f/(1.f+expf(-x)); }
__device__ __forceinline__ int ld_acq(const int* p){
    int v; asm volatile("ld.global.acquire.gpu.b32 %0, [%1];" : "=r"(v) : "l"(p) : "memory");
    return v;
}
__device__ __forceinline__ float4 ldcg4(const float* p){
    return __ldcg(reinterpret_cast<const float4*>(p));
}

// ---------------- shared GEMM panel: C(128x64) += A(m0..,K) * W(n0..,K)^T ---
__device__ __forceinline__ void gemm_panel(
    const float* __restrict__ A, int lda,
    const float* __restrict__ W, int ldw,
    int K, int m0, int n0, int tid,
    float (&cacc)[2][4][4],
    float (&As)[BM][BK+1], float (&Bs)[BN][BK+1])
{
    const int lane = tid & 31, wid = tid >> 5;
    const int wm = wid & 3, wn = wid >> 2;
    const int gid = lane >> 2, tig = lane & 3;

    for (int k0 = 0; k0 < K; k0 += BK) {
        for (int i = tid; i < BM*(BK/4); i += 256) {
            int r = i >> 2, c4 = (i & 3) * 4;
            float4 v = *reinterpret_cast<const float4*>(A + (size_t)(m0+r)*lda + k0 + c4);
            As[r][c4+0]=to_tf32(v.x); As[r][c4+1]=to_tf32(v.y);
            As[r][c4+2]=to_tf32(v.z); As[r][c4+3]=to_tf32(v.w);
        }
        for (int i = tid; i < BN*(BK/4); i += 256) {
            int r = i >> 2, c4 = (i & 3) * 4;
            float4 v = *reinterpret_cast<const float4*>(W + (size_t)(n0+r)*ldw + k0 + c4);
            Bs[r][c4+0]=to_tf32(v.x); Bs[r][c4+1]=to_tf32(v.y);
            Bs[r][c4+2]=to_tf32(v.z); Bs[r][c4+3]=to_tf32(v.w);
        }
        __syncthreads();
        #pragma unroll
        for (int kk = 0; kk < 2; kk++) {
            float a[2][4], bf2[4][2];
            #pragma unroll
            for (int mt = 0; mt < 2; mt++) {
                int rb = wm*32 + mt*16;
                a[mt][0] = As[rb+gid  ][kk*8+tig  ];
                a[mt][1] = As[rb+gid+8][kk*8+tig  ];
                a[mt][2] = As[rb+gid  ][kk*8+tig+4];
                a[mt][3] = As[rb+gid+8][kk*8+tig+4];
            }
            #pragma unroll
            for (int nt = 0; nt < 4; nt++) {
                int nb = wn*32 + nt*8;
                bf2[nt][0] = Bs[nb+gid][kk*8+tig  ];
                bf2[nt][1] = Bs[nb+gid][kk*8+tig+4];
            }
            #pragma unroll
            for (int mt = 0; mt < 2; mt++)
                #pragma unroll
                for (int nt = 0; nt < 4; nt++)
                    mma8(cacc[mt][nt], a[mt], bf2[nt]);
        }
        __syncthreads();
    }
}

// ---------------- phase A: P_g = X_g @ W_g^T + b_g --------------------------
__global__ __launch_bounds__(256)
void gemm_pre(const float* __restrict__ x, const float* __restrict__ xd,
              const float* __restrict__ W0, const float* __restrict__ W1,
              const float* __restrict__ W2, const float* __restrict__ W3,
              const float* __restrict__ W4,
              const float* __restrict__ b0, const float* __restrict__ b1,
              const float* __restrict__ b2, const float* __restrict__ b3,
              const float* __restrict__ b4)
{
    __shared__ float As[BM][BK+1];
    __shared__ float Bs[BN][BK+1];
    const int gate = blockIdx.z;
    const float* A    = (gate == 4) ? xd : x;
    const float* W    = gate==0?W0 : gate==1?W1 : gate==2?W2 : gate==3?W3 : W4;
    const float* bias = gate==0?b0 : gate==1?b1 : gate==2?b2 : gate==3?b3 : b4;
    const int m0 = blockIdx.y * BM;
    const int n0 = blockIdx.x * BN;
    const int tid = threadIdx.x;

    float cacc[2][4][4];
    #pragma unroll
    for (int i=0;i<2;i++) for (int j=0;j<4;j++) for (int k=0;k<4;k++) cacc[i][j][k]=0.f;

    gemm_panel(A, Isz, W, Isz, Isz, m0, n0, tid, cacc, As, Bs);

    const int lane = tid & 31, wid = tid >> 5;
    const int wm = wid & 3, wn = wid >> 2;
    const int gid = lane >> 2, tig = lane & 3;
    #pragma unroll
    for (int mt=0; mt<2; mt++)
        #pragma unroll
        for (int nt=0; nt<4; nt++) {
            int row = m0 + wm*32 + mt*16 + gid;
            int b = row >> 8;
            int tt = row & 255;
            int col = n0 + wn*32 + nt*8 + 2*tig;
            float bv0 = bias[col], bv1 = bias[col+1];
            g_P[gate][tt  ][b][col  ] = cacc[mt][nt][0] + bv0;
            g_P[gate][tt  ][b][col+1] = cacc[mt][nt][1] + bv1;
            g_P[gate][tt+8][b][col  ] = cacc[mt][nt][2] + bv0;
            g_P[gate][tt+8][b][col+1] = cacc[mt][nt][3] + bv1;
        }
}

// ---------------- phase B: persistent recurrence kernel ---------------------
// 128 CTAs, each owns 8 h-columns x 5 gates. Weights live in SMEM for all
// 256 timesteps. Cross-CTA sync via per-producer flags (acquire/release).
#define SBK 32
#define HSTR 36
#define WSTR 1028
#define W_OFF 0
#define HS_OFF 41120                   /* 40*1028 */
#define RED_OFF 50336                  /* HS_OFF + 2*128*36 */
#define SMEM_FLOATS 55584              /* RED_OFF + 4*1312 */

__global__ void __launch_bounds__(256, 1)
lstm_persist(const float* __restrict__ Whi, const float* __restrict__ Whf,
             const float* __restrict__ Whg, const float* __restrict__ Who,
             const float* __restrict__ Whd)
{
    extern __shared__ float sm[];
    const int cb  = blockIdx.x;
    const int h0  = cb * 8;
    const int tid = threadIdx.x, lane = tid & 31, wid = tid >> 5;
    const int gid = lane >> 2, tig = lane & 3;
    const int wm  = wid & 3;
    const int kh  = wid >> 2;

    // ---- load weights into SMEM once (tf32) ----
    for (int i = tid; i < 40*256; i += 256) {
        int row = i >> 8; int c4 = (i & 255) * 4;
        int g = row >> 3, r = row & 7;
        const float* Wg = g==0?Whi : g==1?Whf : g==2?Whg : g==3?Who : Whd;
        float4 v = *reinterpret_cast<const float4*>(Wg + (size_t)(h0+r)*Hsz + c4);
        float* p = &sm[W_OFF + row*WSTR + c4];
        p[0]=to_tf32(v.x); p[1]=to_tf32(v.y); p[2]=to_tf32(v.z); p[3]=to_tf32(v.w);
    }
    __syncthreads();

    const int ar  = tid >> 3;            // h-tile row base
    const int ac4 = (tid & 7) * 4;       // col within 32-wide k tile

    for (int t = 0; t < Tsz; t++) {
        const float* __restrict__ hprev = g_h[t & 1];

        // wait for producer group 0 (h columns 0..255 of this step's input)
        if (wid == 0) {
            const int* fp = &g_flag[lane * 8];
            while (ld_acq(fp) < t) {}
        }
        __syncthreads();

        float4 ra[4];
        #pragma unroll
        for (int j=0; j<4; j++)
            ra[j] = ldcg4(hprev + (size_t)(ar + j*32)*Hsz + ac4);
        #pragma unroll
        for (int j=0; j<4; j++) {
            float* p = &sm[HS_OFF + (ar + j*32)*HSTR + ac4];
            p[0]=to_tf32(ra[j].x); p[1]=to_tf32(ra[j].y);
            p[2]=to_tf32(ra[j].z); p[3]=to_tf32(ra[j].w);
        }
        __syncthreads();

        float cacc[2][5][4];
        #pragma unroll
        for (int mt=0; mt<2; mt++)
            #pragma unroll
            for (int g=0; g<5; g++)
                { cacc[mt][g][0]=0.f; cacc[mt][g][1]=0.f; cacc[mt][g][2]=0.f; cacc[mt][g][3]=0.f; }

        for (int k0 = 0; k0 < Hsz/SBK; k0++) {
            const int buf = k0 & 1;
            if (k0 < Hsz/SBK - 1) {
                const int kn = (k0+1)*SBK;
                if (((k0+1) & 7) == 0) {          // new producer group needed
                    if (wid == 0) {
                        const int* fp = &g_flag[(((k0+1) >> 3)*32 + lane) * 8];
                        while (ld_acq(fp) < t) {}
                    }
                    __syncthreads();
                }
                #pragma unroll
                for (int j=0; j<4; j++)
                    ra[j] = ldcg4(hprev + (size_t)(ar + j*32)*Hsz + kn + ac4);
            }

            const float* HS_ = &sm[HS_OFF + buf*4608];
            const float* WS_ = &sm[W_OFF + k0*SBK];
            #pragma unroll
            for (int kk = 0; kk < 2; kk++) {
                const int kb = kh*16 + kk*8;
                float a[2][4];
                #pragma unroll
                for (int mt=0; mt<2; mt++) {
                    const float* hp = HS_ + (wm*32 + mt*16 + gid)*HSTR + kb;
                    a[mt][0] = hp[tig];
                    a[mt][1] = hp[8*HSTR + tig];
                    a[mt][2] = hp[tig+4];
                    a[mt][3] = hp[8*HSTR + tig+4];
                }
                #pragma unroll
                for (int g=0; g<5; g++) {
                    const float* bp = WS_ + (g*8 + gid)*WSTR + kb;
                    float br[2] = { bp[tig], bp[tig+4] };
                    mma8(cacc[0][g], a[0], br);
                    mma8(cacc[1][g], a[1], br);
                }
            }

            if (k0 < Hsz/SBK - 1) {
                const int nb = buf ^ 1;
                #pragma unroll
                for (int j=0; j<4; j++) {
                    float* p = &sm[HS_OFF + nb*4608 + (ar + j*32)*HSTR + ac4];
                    p[0]=to_tf32(ra[j].x); p[1]=to_tf32(ra[j].y);
                    p[2]=to_tf32(ra[j].z); p[3]=to_tf32(ra[j].w);
                }
            }
            __syncthreads();
        }

        // ---- cross-k-half reduction ----
        if (kh == 1) {
            float* sr = &sm[RED_OFF + wm*1312 + lane*41];
            #pragma unroll
            for (int mt=0; mt<2; mt++)
                #pragma unroll
                for (int g=0; g<5; g++)
                    #pragma unroll
                    for (int r=0; r<4; r++)
                        sr[mt*20 + g*4 + r] = cacc[mt][g][r];
        }
        __syncthreads();

        if (kh == 0) {
            const float* sr = &sm[RED_OFF + wm*1312 + lane*41];
            #pragma unroll
            for (int mt=0; mt<2; mt++)
                #pragma unroll
                for (int g=0; g<5; g++)
                    #pragma unroll
                    for (int r=0; r<4; r++)
                        cacc[mt][g][r] += sr[mt*20 + g*4 + r];

            float* __restrict__ hnext = g_h[(t+1) & 1];
            #pragma unroll
            for (int mt=0; mt<2; mt++)
                #pragma unroll
                for (int r=0; r<4; r++) {
                    int b = wm*32 + mt*16 + gid + ((r >> 1) ? 8 : 0);
                    int h = h0 + 2*tig + (r & 1);
                    size_t pofs = ((size_t)t*Bsz + b)*Hsz + h;
                    float pi = cacc[mt][0][r] + g_P[0][0][0][pofs];
                    float pf = cacc[mt][1][r] + g_P[1][0][0][pofs];
                    float pg = cacc[mt][2][r] + g_P[2][0][0][pofs];
                    float po = cacc[mt][3][r] + g_P[3][0][0][pofs];
                    float pd = cacc[mt][4][r] + g_P[4][0][0][pofs];
                    float iv = sig_(pi), fv = sig_(pf), gv = tanhf(pg);
                    float ov = sig_(po), dv = sig_(pd);
                    float cp = g_c[b*Hsz + h];
                    float cn = fv*cp + iv*gv + dv;
                    float hn = ov * tanhf(cn);
                    g_c[b*Hsz + h] = cn;
                    hnext[b*Hsz + h] = hn;
                    g_HS[((size_t)b*Tsz + t)*Hsz + h] = hn;
                }
        }
        __syncthreads();

        if (tid == 0) {
            __threadfence();                     // release h/c writes
            atomicExch(&g_flag[cb*8], t + 1);    // publish step t output
        }
    }
}

// ---------------- phase C: y = tanh(X@Wro^T + HS@Who^T + Wrb) ---------------
__global__ __launch_bounds__(256)
void gemm_out(const float* __restrict__ x, const float* __restrict__ Wro,
              const float* __restrict__ Who, const float* __restrict__ Wrb,
              float* __restrict__ y)
{
    __shared__ float As[BM][BK+1];
    __shared__ float Bs[BN][BK+1];
    const int m0 = blockIdx.y * BM;
    const int n0 = blockIdx.x * BN;
    const int tid = threadIdx.x;

    float cacc[2][4][4];
    #pragma unroll
    for (int i=0;i<2;i++) for (int j=0;j<4;j++) for (int k=0;k<4;k++) cacc[i][j][k]=0.f;

    gemm_panel(x,        Isz, Wro, Isz, Isz, m0, n0, tid, cacc, As, Bs);
    gemm_panel(&g_HS[0], Hsz, Who, Hsz, Hsz, m0, n0, tid, cacc, As, Bs);

    const int lane = tid & 31, wid = tid >> 5;
    const int wm = wid & 3, wn = wid >> 2;
    const int gid = lane >> 2, tig = lane & 3;
    #pragma unroll
    for (int mt=0; mt<2; mt++)
        #pragma unroll
        for (int nt=0; nt<4; nt++) {
            int row = m0 + wm*32 + mt*16 + gid;
            int col = n0 + wn*32 + nt*8 + 2*tig;
            float bv0 = Wrb[col], bv1 = Wrb[col+1];
            y[(size_t)row*Hsz + col  ]     = tanhf(cacc[mt][nt][0] + bv0);
            y[(size_t)row*Hsz + col+1]     = tanhf(cacc[mt][nt][1] + bv1);
            y[(size_t)(row+8)*Hsz + col  ] = tanhf(cacc[mt][nt][2] + bv0);
            y[(size_t)(row+8)*Hsz + col+1] = tanhf(cacc[mt][nt][3] + bv1);
        }
}

// ---------------- small state init / tail copy ------------------------------
__global__ void init_state(const float* __restrict__ hidden, const float* __restrict__ cell){
    int i = blockIdx.x * 256 + threadIdx.x;
    g_h[0][i] = hidden[i];
    g_c[i]    = cell[i];
    if (blockIdx.x == 0 && threadIdx.x < Bsz) g_flag[threadIdx.x * 8] = 0;
}
__global__ void write_tail(float* __restrict__ out){
    int i = blockIdx.x * 256 + threadIdx.x;
    out[(size_t)Bsz*Tsz*Hsz + i]              = g_h[0][i];
    out[(size_t)Bsz*Tsz*Hsz + Bsz*Hsz + i]    = g_c[i];
}

// ---------------- launcher ---------------------------------------------------
extern "C" void kernel_launch(void* const* d_in, const int* in_sizes, int n_in,
                              void* d_out, int out_size)
{
    const float *x, *xd, *hidden, *cell;
    const float *Wii,*Wif,*Wig,*Wio,*Wid,*Wro,*Whi,*Whf,*Whg,*Who,*Whd;
    const float *bi,*bf,*bg,*bo,*bd,*Wrb;

    x      = (const float*)d_in[0];
    xd     = (const float*)d_in[1];
    hidden = (const float*)d_in[2];
    cell   = (const float*)d_in[3];

    if (in_sizes[5] == Hsz*Isz) {
        Wii=(const float*)d_in[4];  Wif=(const float*)d_in[5];  Wig=(const float*)d_in[6];
        Wio=(const float*)d_in[7];  Wid=(const float*)d_in[8];  Wro=(const float*)d_in[9];
        Whi=(const float*)d_in[10]; Whf=(const float*)d_in[11]; Whg=(const float*)d_in[12];
        Who=(const float*)d_in[13]; Whd=(const float*)d_in[14];
        bi=(const float*)d_in[15];  bf=(const float*)d_in[16];  bg=(const float*)d_in[17];
        bo=(const float*)d_in[18];  bd=(const float*)d_in[19];  Wrb=(const float*)d_in[20];
    } else {
        Wii=(const float*)d_in[4];  Whi=(const float*)d_in[5];  bi =(const float*)d_in[6];
        Wif=(const float*)d_in[7];  Whf=(const float*)d_in[8];  bf =(const float*)d_in[9];
        Wig=(const float*)d_in[10]; Whg=(const float*)d_in[11]; bg =(const float*)d_in[12];
        Wio=(const float*)d_in[13]; Who=(const float*)d_in[14]; bo =(const float*)d_in[15];
        Wid=(const float*)d_in[16]; Whd=(const float*)d_in[17]; bd =(const float*)d_in[18];
        Wro=(const float*)d_in[19]; Wrb=(const float*)d_in[20];
    }

    float* out = (float*)d_out;

    cudaFuncSetAttribute(lstm_persist, cudaFuncAttributeMaxDynamicSharedMemorySize,
                         SMEM_FLOATS * (int)sizeof(float));

    init_state<<<(Bsz*Hsz)/256, 256>>>(hidden, cell);

    dim3 gpre(Hsz/BN, Mpre/BM, 5);
    gemm_pre<<<gpre, 256>>>(x, xd, Wii, Wif, Wig, Wio, Wid, bi, bf, bg, bo, bd);

    lstm_persist<<<Bsz, 256, SMEM_FLOATS * (int)sizeof(float)>>>(Whi, Whf, Whg, Who, Whd);

    gemm_out<<<dim3(Hsz/BN, Mpre/BM), 256>>>(x, Wro, Who, Wrb, out);

    write_tail<<<(Bsz*Hsz)/256, 256>>>(out);
}

// round 4
// speedup vs baseline: 3.2563x; 1.0032x over previous
#include <cuda_runtime.h>
#include <math.h>

#define Bsz 128
#define Tsz 256
#define Isz 512
#define Hsz 1024
#define Mpre (Bsz*Tsz)

#define BM 128
#define BN 64
#define BK 16

// ---------------- scratch (static device allocations; no cudaMalloc) --------
__device__ float g_P[5][Tsz][Bsz][Hsz];      // gate preactivations, [g][t][b][h]
__device__ float g_HS[(size_t)Mpre*Hsz];     // all hidden states, (b*T+t, h)
__device__ float g_h[2][Bsz*Hsz];            // ping-pong hidden
__device__ float g_c[Bsz*Hsz];               // cell state
__device__ int   g_flag[Bsz*8];              // producer flags, 32B padded

// ---------------- helpers ---------------------------------------------------
__device__ __forceinline__ float to_tf32(float x){
    float r; asm("cvt.rna.tf32.f32 %0, %1;" : "=f"(r) : "f"(x)); return r;
}
__device__ __forceinline__ void mma8(float c[4], const float a[4], const float b[2]){
    asm volatile("mma.sync.aligned.m16n8k8.row.col.f32.tf32.tf32.f32 "
        "{%0,%1,%2,%3},{%4,%5,%6,%7},{%8,%9},{%0,%1,%2,%3};"
        : "+f"(c[0]),"+f"(c[1]),"+f"(c[2]),"+f"(c[3])
        : "r"(__float_as_uint(a[0])),"r"(__float_as_uint(a[1])),
          "r"(__float_as_uint(a[2])),"r"(__float_as_uint(a[3])),
          "r"(__float_as_uint(b[0])),"r"(__float_as_uint(b[1])));
}
__device__ __forceinline__ float sig_(float x){ return 1.f/(1.f+expf(-x)); }
__device__ __forceinline__ int ld_acq(const int* p){
    int v; asm volatile("ld.global.acquire.gpu.b32 %0, [%1];" : "=r"(v) : "l"(p) : "memory");
    return v;
}
__device__ __forceinline__ float4 ldcg4(const float* p){
    return __ldcg(reinterpret_cast<const float4*>(p));
}

// ---------------- shared GEMM panel: C(128x64) += A(m0..,K) * W(n0..,K)^T ---
__device__ __forceinline__ void gemm_panel(
    const float* __restrict__ A, int lda,
    const float* __restrict__ W, int ldw,
    int K, int m0, int n0, int tid,
    float (&cacc)[2][4][4],
    float (&As)[BM][BK+1], float (&Bs)[BN][BK+1])
{
    const int lane = tid & 31, wid = tid >> 5;
    const int wm = wid & 3, wn = wid >> 2;
    const int gid = lane >> 2, tig = lane & 3;

    for (int k0 = 0; k0 < K; k0 += BK) {
        for (int i = tid; i < BM*(BK/4); i += 256) {
            int r = i >> 2, c4 = (i & 3) * 4;
            float4 v = *reinterpret_cast<const float4*>(A + (size_t)(m0+r)*lda + k0 + c4);
            As[r][c4+0]=to_tf32(v.x); As[r][c4+1]=to_tf32(v.y);
            As[r][c4+2]=to_tf32(v.z); As[r][c4+3]=to_tf32(v.w);
        }
        for (int i = tid; i < BN*(BK/4); i += 256) {
            int r = i >> 2, c4 = (i & 3) * 4;
            float4 v = *reinterpret_cast<const float4*>(W + (size_t)(n0+r)*ldw + k0 + c4);
            Bs[r][c4+0]=to_tf32(v.x); Bs[r][c4+1]=to_tf32(v.y);
            Bs[r][c4+2]=to_tf32(v.z); Bs[r][c4+3]=to_tf32(v.w);
        }
        __syncthreads();
        #pragma unroll
        for (int kk = 0; kk < 2; kk++) {
            float a[2][4], bf2[4][2];
            #pragma unroll
            for (int mt = 0; mt < 2; mt++) {
                int rb = wm*32 + mt*16;
                a[mt][0] = As[rb+gid  ][kk*8+tig  ];
                a[mt][1] = As[rb+gid+8][kk*8+tig  ];
                a[mt][2] = As[rb+gid  ][kk*8+tig+4];
                a[mt][3] = As[rb+gid+8][kk*8+tig+4];
            }
            #pragma unroll
            for (int nt = 0; nt < 4; nt++) {
                int nb = wn*32 + nt*8;
                bf2[nt][0] = Bs[nb+gid][kk*8+tig  ];
                bf2[nt][1] = Bs[nb+gid][kk*8+tig+4];
            }
            #pragma unroll
            for (int mt = 0; mt < 2; mt++)
                #pragma unroll
                for (int nt = 0; nt < 4; nt++)
                    mma8(cacc[mt][nt], a[mt], bf2[nt]);
        }
        __syncthreads();
    }
}

// ---------------- phase A: P_g = X_g @ W_g^T + b_g --------------------------
__global__ __launch_bounds__(256)
void gemm_pre(const float* __restrict__ x, const float* __restrict__ xd,
              const float* __restrict__ W0, const float* __restrict__ W1,
              const float* __restrict__ W2, const float* __restrict__ W3,
              const float* __restrict__ W4,
              const float* __restrict__ b0, const float* __restrict__ b1,
              const float* __restrict__ b2, const float* __restrict__ b3,
              const float* __restrict__ b4)
{
    __shared__ float As[BM][BK+1];
    __shared__ float Bs[BN][BK+1];
    const int gate = blockIdx.z;
    const float* A    = (gate == 4) ? xd : x;
    const float* W    = gate==0?W0 : gate==1?W1 : gate==2?W2 : gate==3?W3 : W4;
    const float* bias = gate==0?b0 : gate==1?b1 : gate==2?b2 : gate==3?b3 : b4;
    const int m0 = blockIdx.y * BM;
    const int n0 = blockIdx.x * BN;
    const int tid = threadIdx.x;

    float cacc[2][4][4];
    #pragma unroll
    for (int i=0;i<2;i++) for (int j=0;j<4;j++) for (int k=0;k<4;k++) cacc[i][j][k]=0.f;

    gemm_panel(A, Isz, W, Isz, Isz, m0, n0, tid, cacc, As, Bs);

    const int lane = tid & 31, wid = tid >> 5;
    const int wm = wid & 3, wn = wid >> 2;
    const int gid = lane >> 2, tig = lane & 3;
    #pragma unroll
    for (int mt=0; mt<2; mt++)
        #pragma unroll
        for (int nt=0; nt<4; nt++) {
            int row = m0 + wm*32 + mt*16 + gid;
            int b = row >> 8;
            int tt = row & 255;
            int col = n0 + wn*32 + nt*8 + 2*tig;
            float bv0 = bias[col], bv1 = bias[col+1];
            g_P[gate][tt  ][b][col  ] = cacc[mt][nt][0] + bv0;
            g_P[gate][tt  ][b][col+1] = cacc[mt][nt][1] + bv1;
            g_P[gate][tt+8][b][col  ] = cacc[mt][nt][2] + bv0;
            g_P[gate][tt+8][b][col+1] = cacc[mt][nt][3] + bv1;
        }
}

// ---------------- phase B: persistent recurrence kernel ---------------------
// 128 CTAs, each owns 8 h-columns x 5 gates. Weights live in SMEM for all
// 256 timesteps. Cross-CTA sync via per-producer flags (acquire/release).
#define SBK 32
#define HSTR 36
#define WSTR 1028
#define W_OFF 0
#define HS_OFF 41120                   /* 40*1028 */
#define RED_OFF 50336                  /* HS_OFF + 2*128*36 */
#define SMEM_FLOATS 55584              /* RED_OFF + 4*1312 */

__global__ void __launch_bounds__(256, 1)
lstm_persist(const float* __restrict__ Whi, const float* __restrict__ Whf,
             const float* __restrict__ Whg, const float* __restrict__ Who,
             const float* __restrict__ Whd)
{
    extern __shared__ float sm[];
    const int cb  = blockIdx.x;
    const int h0  = cb * 8;
    const int tid = threadIdx.x, lane = tid & 31, wid = tid >> 5;
    const int gid = lane >> 2, tig = lane & 3;
    const int wm  = wid & 3;
    const int kh  = wid >> 2;

    // ---- load weights into SMEM once (tf32) ----
    for (int i = tid; i < 40*256; i += 256) {
        int row = i >> 8; int c4 = (i & 255) * 4;
        int g = row >> 3, r = row & 7;
        const float* Wg = g==0?Whi : g==1?Whf : g==2?Whg : g==3?Who : Whd;
        float4 v = *reinterpret_cast<const float4*>(Wg + (size_t)(h0+r)*Hsz + c4);
        float* p = &sm[W_OFF + row*WSTR + c4];
        p[0]=to_tf32(v.x); p[1]=to_tf32(v.y); p[2]=to_tf32(v.z); p[3]=to_tf32(v.w);
    }
    __syncthreads();

    const int ar  = tid >> 3;            // h-tile row base
    const int ac4 = (tid & 7) * 4;       // col within 32-wide k tile

    for (int t = 0; t < Tsz; t++) {
        const float* __restrict__ hprev = g_h[t & 1];

        // wait for producer group 0 (h columns 0..255 of this step's input)
        if (wid == 0) {
            const int* fp = &g_flag[lane * 8];
            while (ld_acq(fp) < t) {}
        }
        __syncthreads();

        float4 ra[4];
        #pragma unroll
        for (int j=0; j<4; j++)
            ra[j] = ldcg4(hprev + (size_t)(ar + j*32)*Hsz + ac4);
        #pragma unroll
        for (int j=0; j<4; j++) {
            float* p = &sm[HS_OFF + (ar + j*32)*HSTR + ac4];
            p[0]=to_tf32(ra[j].x); p[1]=to_tf32(ra[j].y);
            p[2]=to_tf32(ra[j].z); p[3]=to_tf32(ra[j].w);
        }
        __syncthreads();

        float cacc[2][5][4];
        #pragma unroll
        for (int mt=0; mt<2; mt++)
            #pragma unroll
            for (int g=0; g<5; g++)
                { cacc[mt][g][0]=0.f; cacc[mt][g][1]=0.f; cacc[mt][g][2]=0.f; cacc[mt][g][3]=0.f; }

        for (int k0 = 0; k0 < Hsz/SBK; k0++) {
            const int buf = k0 & 1;
            if (k0 < Hsz/SBK - 1) {
                const int kn = (k0+1)*SBK;
                if (((k0+1) & 7) == 0) {          // new producer group needed
                    if (wid == 0) {
                        const int* fp = &g_flag[(((k0+1) >> 3)*32 + lane) * 8];
                        while (ld_acq(fp) < t) {}
                    }
                    __syncthreads();
                }
                #pragma unroll
                for (int j=0; j<4; j++)
                    ra[j] = ldcg4(hprev + (size_t)(ar + j*32)*Hsz + kn + ac4);
            }

            const float* HS_ = &sm[HS_OFF + buf*4608];
            const float* WS_ = &sm[W_OFF + k0*SBK];
            #pragma unroll
            for (int kk = 0; kk < 2; kk++) {
                const int kb = kh*16 + kk*8;
                float a[2][4];
                #pragma unroll
                for (int mt=0; mt<2; mt++) {
                    const float* hp = HS_ + (wm*32 + mt*16 + gid)*HSTR + kb;
                    a[mt][0] = hp[tig];
                    a[mt][1] = hp[8*HSTR + tig];
                    a[mt][2] = hp[tig+4];
                    a[mt][3] = hp[8*HSTR + tig+4];
                }
                #pragma unroll
                for (int g=0; g<5; g++) {
                    const float* bp = WS_ + (g*8 + gid)*WSTR + kb;
                    float br[2] = { bp[tig], bp[tig+4] };
                    mma8(cacc[0][g], a[0], br);
                    mma8(cacc[1][g], a[1], br);
                }
            }

            if (k0 < Hsz/SBK - 1) {
                const int nb = buf ^ 1;
                #pragma unroll
                for (int j=0; j<4; j++) {
                    float* p = &sm[HS_OFF + nb*4608 + (ar + j*32)*HSTR + ac4];
                    p[0]=to_tf32(ra[j].x); p[1]=to_tf32(ra[j].y);
                    p[2]=to_tf32(ra[j].z); p[3]=to_tf32(ra[j].w);
                }
            }
            __syncthreads();
        }

        // ---- cross-k-half reduction ----
        if (kh == 1) {
            float* sr = &sm[RED_OFF + wm*1312 + lane*41];
            #pragma unroll
            for (int mt=0; mt<2; mt++)
                #pragma unroll
                for (int g=0; g<5; g++)
                    #pragma unroll
                    for (int r=0; r<4; r++)
                        sr[mt*20 + g*4 + r] = cacc[mt][g][r];
        }
        __syncthreads();

        if (kh == 0) {
            const float* sr = &sm[RED_OFF + wm*1312 + lane*41];
            #pragma unroll
            for (int mt=0; mt<2; mt++)
                #pragma unroll
                for (int g=0; g<5; g++)
                    #pragma unroll
                    for (int r=0; r<4; r++)
                        cacc[mt][g][r] += sr[mt*20 + g*4 + r];

            float* __restrict__ hnext = g_h[(t+1) & 1];
            #pragma unroll
            for (int mt=0; mt<2; mt++)
                #pragma unroll
                for (int r=0; r<4; r++) {
                    int b = wm*32 + mt*16 + gid + ((r >> 1) ? 8 : 0);
                    int h = h0 + 2*tig + (r & 1);
                    size_t pofs = ((size_t)t*Bsz + b)*Hsz + h;
                    float pi = cacc[mt][0][r] + g_P[0][0][0][pofs];
                    float pf = cacc[mt][1][r] + g_P[1][0][0][pofs];
                    float pg = cacc[mt][2][r] + g_P[2][0][0][pofs];
                    float po = cacc[mt][3][r] + g_P[3][0][0][pofs];
                    float pd = cacc[mt][4][r] + g_P[4][0][0][pofs];
                    float iv = sig_(pi), fv = sig_(pf), gv = tanhf(pg);
                    float ov = sig_(po), dv = sig_(pd);
                    float cp = g_c[b*Hsz + h];
                    float cn = fv*cp + iv*gv + dv;
                    float hn = ov * tanhf(cn);
                    g_c[b*Hsz + h] = cn;
                    hnext[b*Hsz + h] = hn;
                    g_HS[((size_t)b*Tsz + t)*Hsz + h] = hn;
                }
        }
        __syncthreads();

        if (tid == 0) {
            __threadfence();                     // release h/c writes
            atomicExch(&g_flag[cb*8], t + 1);    // publish step t output
        }
    }
}

// ---------------- phase C: y = tanh(X@Wro^T + HS@Who^T + Wrb) ---------------
__global__ __launch_bounds__(256)
void gemm_out(const float* __restrict__ x, const float* __restrict__ Wro,
              const float* __restrict__ Who, const float* __restrict__ Wrb,
              float* __restrict__ y)
{
    __shared__ float As[BM][BK+1];
    __shared__ float Bs[BN][BK+1];
    const int m0 = blockIdx.y * BM;
    const int n0 = blockIdx.x * BN;
    const int tid = threadIdx.x;

    float cacc[2][4][4];
    #pragma unroll
    for (int i=0;i<2;i++) for (int j=0;j<4;j++) for (int k=0;k<4;k++) cacc[i][j][k]=0.f;

    gemm_panel(x,        Isz, Wro, Isz, Isz, m0, n0, tid, cacc, As, Bs);
    gemm_panel(&g_HS[0], Hsz, Who, Hsz, Hsz, m0, n0, tid, cacc, As, Bs);

    const int lane = tid & 31, wid = tid >> 5;
    const int wm = wid & 3, wn = wid >> 2;
    const int gid = lane >> 2, tig = lane & 3;
    #pragma unroll
    for (int mt=0; mt<2; mt++)
        #pragma unroll
        for (int nt=0; nt<4; nt++) {
            int row = m0 + wm*32 + mt*16 + gid;
            int col = n0 + wn*32 + nt*8 + 2*tig;
            float bv0 = Wrb[col], bv1 = Wrb[col+1];
            y[(size_t)row*Hsz + col  ]     = tanhf(cacc[mt][nt][0] + bv0);
            y[(size_t)row*Hsz + col+1]     = tanhf(cacc[mt][nt][1] + bv1);
            y[(size_t)(row+8)*Hsz + col  ] = tanhf(cacc[mt][nt][2] + bv0);
            y[(size_t)(row+8)*Hsz + col+1] = tanhf(cacc[mt][nt][3] + bv1);
        }
}

// ---------------- small state init / tail copy ------------------------------
__global__ void init_state(const float* __restrict__ hidden, const float* __restrict__ cell){
    int i = blockIdx.x * 256 + threadIdx.x;
    g_h[0][i] = hidden[i];
    g_c[i]    = cell[i];
    if (blockIdx.x == 0 && threadIdx.x < Bsz) g_flag[threadIdx.x * 8] = 0;
}
__global__ void write_tail(float* __restrict__ out){
    int i = blockIdx.x * 256 + threadIdx.x;
    out[(size_t)Bsz*Tsz*Hsz + i]              = g_h[0][i];
    out[(size_t)Bsz*Tsz*Hsz + Bsz*Hsz + i]    = g_c[i];
}

// ---------------- launcher ---------------------------------------------------
extern "C" void kernel_launch(void* const* d_in, const int* in_sizes, int n_in,
                              void* d_out, int out_size)
{
    const float *x, *xd, *hidden, *cell;
    const float *Wii,*Wif,*Wig,*Wio,*Wid,*Wro,*Whi,*Whf,*Whg,*Who,*Whd;
    const float *bi,*bf,*bg,*bo,*bd,*Wrb;

    x      = (const float*)d_in[0];
    xd     = (const float*)d_in[1];
    hidden = (const float*)d_in[2];
    cell   = (const float*)d_in[3];

    if (in_sizes[5] == Hsz*Isz) {
        Wii=(const float*)d_in[4];  Wif=(const float*)d_in[5];  Wig=(const float*)d_in[6];
        Wio=(const float*)d_in[7];  Wid=(const float*)d_in[8];  Wro=(const float*)d_in[9];
        Whi=(const float*)d_in[10]; Whf=(const float*)d_in[11]; Whg=(const float*)d_in[12];
        Who=(const float*)d_in[13]; Whd=(const float*)d_in[14];
        bi=(const float*)d_in[15];  bf=(const float*)d_in[16];  bg=(const float*)d_in[17];
        bo=(const float*)d_in[18];  bd=(const float*)d_in[19];  Wrb=(const float*)d_in[20];
    } else {
        Wii=(const float*)d_in[4];  Whi=(const float*)d_in[5];  bi =(const float*)d_in[6];
        Wif=(const float*)d_in[7];  Whf=(const float*)d_in[8];  bf =(const float*)d_in[9];
        Wig=(const float*)d_in[10]; Whg=(const float*)d_in[11]; bg =(const float*)d_in[12];
        Wio=(const float*)d_in[13]; Who=(const float*)d_in[14]; bo =(const float*)d_in[15];
        Wid=(const float*)d_in[16]; Whd=(const float*)d_in[17]; bd =(const float*)d_in[18];
        Wro=(const float*)d_in[19]; Wrb=(const float*)d_in[20];
    }

    float* out = (float*)d_out;

    cudaFuncSetAttribute(lstm_persist, cudaFuncAttributeMaxDynamicSharedMemorySize,
                         SMEM_FLOATS * (int)sizeof(float));

    init_state<<<(Bsz*Hsz)/256, 256>>>(hidden, cell);

    dim3 gpre(Hsz/BN, Mpre/BM, 5);
    gemm_pre<<<gpre, 256>>>(x, xd, Wii, Wif, Wig, Wio, Wid, bi, bf, bg, bo, bd);

    lstm_persist<<<Bsz, 256, SMEM_FLOATS * (int)sizeof(float)>>>(Whi, Whf, Whg, Who, Whd);

    gemm_out<<<dim3(Hsz/BN, Mpre/BM), 256>>>(x, Wro, Who, Wrb, out);

    write_tail<<<(Bsz*Hsz)/256, 256>>>(out);
}